// round 1
// baseline (speedup 1.0000x reference)
#include <cuda_runtime.h>

#define NJ   24
#define HIDD 7
#define FEATD 6
#define BATCH 500000
#define PAIRS (BATCH/2)
#define WPJ  104            // float2 slots per joint: 7(b1) + 49(W1) + 6(b2) + 42(W2)
#define WTOT (NJ*WPJ)       // 2496

typedef unsigned long long u64;

__device__ __forceinline__ u64 pk2(float a, float b) {
    u64 r; asm("mov.b64 %0, {%1,%2};" : "=l"(r) : "f"(a), "f"(b)); return r;
}
__device__ __forceinline__ void upk2(u64 v, float& a, float& b) {
    asm("mov.b64 {%0,%1}, %2;" : "=f"(a), "=f"(b) : "l"(v));
}
// Packed dual-FMA (Blackwell f32x2 pipe): d = a*b + c per 32-bit half.
__device__ __forceinline__ u64 ffma2(u64 a, u64 b, u64 c) {
    u64 d; asm("fma.rn.f32x2 %0, %1, %2, %3;" : "=l"(d) : "l"(a), "l"(b), "l"(c)); return d;
}

__global__ __launch_bounds__(256, 1)
void se1d_kernel(const float* __restrict__ x,
                 const float* __restrict__ W1, const float* __restrict__ b1,
                 const float* __restrict__ W2, const float* __restrict__ b2,
                 float* __restrict__ out)
{
    // Weights in shared, duplicated {w,w} pairs, laid out in exact consumption order.
    __shared__ u64 sw[WTOT];
    for (int idx = threadIdx.x; idx < WTOT; idx += 256) {
        int j = idx / WPJ;
        int o = idx - j * WPJ;
        float v;
        if (o < 7)        v = b1[j*7 + o];
        else if (o < 56)  v = W1[j*49 + (o-7)];      // row-major [r][c]
        else if (o < 62)  v = b2[j*6 + (o-56)];
        else              v = W2[j*42 + (o-62)];     // row-major [r][c]
        sw[idx] = pk2(v, v);
    }
    __syncthreads();

    int pair = blockIdx.x * 256 + threadIdx.x;
    if (pair >= PAIRS) return;

    const long r0 = (long)pair * 2;
    const float4* xr0 = (const float4*)(x + r0 * 24);        // rows 2t, 2t+1: 192B contiguous
    const float4* xr1 = (const float4*)(x + r0 * 24 + 24);
    float* o0 = out + r0 * 144;
    float* o1 = o0 + 144;

    // Load both rows of x (coalesced float4), pack into f32x2 pairs.
    u64 xp[NJ];
    #pragma unroll
    for (int q = 0; q < 6; q++) {
        float4 a = xr0[q];
        float4 b = xr1[q];
        xp[q*4+0] = pk2(a.x, b.x);
        xp[q*4+1] = pk2(a.y, b.y);
        xp[q*4+2] = pk2(a.z, b.z);
        xp[q*4+3] = pk2(a.w, b.w);
    }

    const int PAR[NJ] = {-1,0,0,0,1,2,3,4,5,6,7,8,9,9,9,12,13,14,16,17,18,19,20,21};

    u64 feat[NJ][FEATD];   // fully unrolled -> register-promoted with liveness
    float s0[12], s1[12];  // 2-joint output staging (row0 / row1 scalars)

    #pragma unroll
    for (int j = 0; j < NJ; j++) {
        const u64* wj = sw + j * WPJ;

        u64 inp[HIDD];
        inp[0] = xp[j];
        {
            const int p = PAR[j];
            #pragma unroll
            for (int c = 0; c < FEATD; c++)
                inp[c+1] = (p >= 0) ? feat[p][c] : 0ull;   // folds at compile time
        }

        // Layer 1: h = relu(W1 @ inp + b1), 7x7
        u64 h[HIDD];
        #pragma unroll
        for (int r = 0; r < HIDD; r++) {
            u64 acc = wj[r];                       // b1 pair
            #pragma unroll
            for (int c = 0; c < HIDD; c++)
                acc = ffma2(wj[7 + r*7 + c], inp[c], acc);
            float ax, ay; upk2(acc, ax, ay);
            h[r] = pk2(fmaxf(ax, 0.f), fmaxf(ay, 0.f));
        }

        // Layer 2: f = relu(W2 @ h + b2), 6x7
        #pragma unroll
        for (int r = 0; r < FEATD; r++) {
            u64 acc = wj[56 + r];                  // b2 pair
            #pragma unroll
            for (int c = 0; c < HIDD; c++)
                acc = ffma2(wj[62 + r*7 + c], h[c], acc);
            float ax, ay; upk2(acc, ax, ay);
            ax = fmaxf(ax, 0.f);
            ay = fmaxf(ay, 0.f);
            feat[j][r] = pk2(ax, ay);
            s0[(j & 1) * 6 + r] = ax;
            s1[(j & 1) * 6 + r] = ay;
        }

        // Flush 2 joints (12 floats/row) as 3 aligned STG.128 per row.
        if (j & 1) {
            const int base = (j - 1) * 6;
            *(float4*)(o0 + base + 0) = make_float4(s0[0], s0[1], s0[2],  s0[3]);
            *(float4*)(o0 + base + 4) = make_float4(s0[4], s0[5], s0[6],  s0[7]);
            *(float4*)(o0 + base + 8) = make_float4(s0[8], s0[9], s0[10], s0[11]);
            *(float4*)(o1 + base + 0) = make_float4(s1[0], s1[1], s1[2],  s1[3]);
            *(float4*)(o1 + base + 4) = make_float4(s1[4], s1[5], s1[6],  s1[7]);
            *(float4*)(o1 + base + 8) = make_float4(s1[8], s1[9], s1[10], s1[11]);
        }
    }
}

extern "C" void kernel_launch(void* const* d_in, const int* in_sizes, int n_in,
                              void* d_out, int out_size)
{
    const float* x  = (const float*)d_in[0];
    const float* W1 = (const float*)d_in[1];
    const float* b1 = (const float*)d_in[2];
    const float* W2 = (const float*)d_in[3];
    const float* b2 = (const float*)d_in[4];
    float* out = (float*)d_out;

    const int blocks = (PAIRS + 255) / 256;
    se1d_kernel<<<blocks, 256>>>(x, W1, b1, W2, b2, out);
}